// round 14
// baseline (speedup 1.0000x reference)
#include <cuda_runtime.h>
#include <cuda_bf16.h>
#include <math.h>

#define N_DB   200000
#define D_EMB  512
#define TOP_K  32

// ---- Stage A: pure streaming distances ----
#define TPB_A  256
#define NBLK_A 888                               // 6 CTAs/SM (regs=40 -> occ lim 6)
#define WARPS_A (NBLK_A * (TPB_A / 32))

// histogram: key = float_bits >> 18 (monotone for d >= 0), 8192 bins
#define HSHIFT 18
#define NBINS  8192

// ---- Stage H: histogram build ----
#define TPB_H  1024
#define NBLK_H 148
#define ROWS_H ((N_DB + NBLK_H - 1) / NBLK_H)    // 1352

// ---- Stage C: threshold + compaction + (last block) selection ----
#define TPB_C  1024
#define NBLK_C 148
#define ROWS_C ROWS_H
#define BPT    (NBINS / TPB_C)                   // 8 bins per thread

#define CAP    4096
#define TPB_F  128

// Scratch (allocation-free rule: __device__ globals; zero-initialized at load)
__device__ float g_dist[N_DB];
__device__ int   g_hist[NBINS];
__device__ int   g_cnt;
__device__ int   g_done;
__device__ float g_cd[CAP];
__device__ int   g_ci[CAP];
__device__ int   g_sel_i[TOP_K];
__device__ float g_sel_d[TOP_K];

// ---------------------------------------------------------------------------
// Stage A: pure streaming. One warp per row; 16 floats/lane in float4s via
// __ldcs (evict-first), shuffle-reduce, lane0 stores squared distance.
// ---------------------------------------------------------------------------
__global__ void __launch_bounds__(TPB_A)
knn_dist(const float* __restrict__ x, const float* __restrict__ emb)
{
    const int lane = threadIdx.x & 31;
    const int gw   = blockIdx.x * (TPB_A / 32) + (threadIdx.x >> 5);

    const float4* x4 = (const float4*)x;
    const float4 q0 = x4[lane];
    const float4 q1 = x4[32 + lane];
    const float4 q2 = x4[64 + lane];
    const float4 q3 = x4[96 + lane];

    for (int r = gw; r < N_DB; r += WARPS_A) {
        const float4* p = (const float4*)(emb + (size_t)r * D_EMB);
        float4 v0 = __ldcs(p + lane);
        float4 v1 = __ldcs(p + 32 + lane);
        float4 v2 = __ldcs(p + 64 + lane);
        float4 v3 = __ldcs(p + 96 + lane);

        float acc, d;
        d = v0.x - q0.x; acc  = d * d;
        d = v0.y - q0.y; acc += d * d;
        d = v0.z - q0.z; acc += d * d;
        d = v0.w - q0.w; acc += d * d;
        d = v1.x - q1.x; acc += d * d;
        d = v1.y - q1.y; acc += d * d;
        d = v1.z - q1.z; acc += d * d;
        d = v1.w - q1.w; acc += d * d;
        d = v2.x - q2.x; acc += d * d;
        d = v2.y - q2.y; acc += d * d;
        d = v2.z - q2.z; acc += d * d;
        d = v2.w - q2.w; acc += d * d;
        d = v3.x - q3.x; acc += d * d;
        d = v3.y - q3.y; acc += d * d;
        d = v3.z - q3.z; acc += d * d;
        d = v3.w - q3.w; acc += d * d;

        #pragma unroll
        for (int o = 16; o > 0; o >>= 1)
            acc += __shfl_down_sync(0xffffffffu, acc, o);
        if (lane == 0) g_dist[r] = acc;
    }
}

// ---------------------------------------------------------------------------
// Stage H: build the global histogram from g_dist (L2-hot, 800 KB).
// ---------------------------------------------------------------------------
__global__ void __launch_bounds__(TPB_H)
knn_hist()
{
    __shared__ int sh[NBINS];                    // 32 KB

    const int tid = threadIdx.x;
    for (int i = tid; i < NBINS; i += TPB_H) sh[i] = 0;
    __syncthreads();

    const int base = blockIdx.x * ROWS_H;
    const int rows = min(ROWS_H, N_DB - base);
    for (int j = tid; j < rows; j += TPB_H) {
        float d = g_dist[base + j];
        atomicAdd(&sh[__float_as_uint(d) >> HSHIFT], 1);
    }
    __syncthreads();

    for (int i = tid; i < NBINS; i += TPB_H) {
        int v = sh[i];
        if (v) atomicAdd(&g_hist[i], v);
    }
}

// ---------------------------------------------------------------------------
// Stage C: each block prefix-scans the histogram -> threshold bin b*, then
// compacts its slice of g_dist into the candidate buffer. The LAST block to
// finish (done-counter) additionally runs the rank-based top-32 selection
// inline over the globally-visible candidates (fences ordered via acq/rel
// atomics), writing g_sel_i / g_sel_d. Saves a whole kernel launch.
// ---------------------------------------------------------------------------
__global__ void __launch_bounds__(TPB_C)
knn_compact_select()
{
    __shared__ int   sp[TPB_C];
    __shared__ int   s_bstar;
    __shared__ int   s_last;
    __shared__ float cd[CAP];
    __shared__ int   ci[CAP];

    const int tid = threadIdx.x;

    int bins[BPT];
    int s = 0;
    const int b0 = tid * BPT;
    #pragma unroll
    for (int i = 0; i < BPT; i++) { bins[i] = g_hist[b0 + i]; s += bins[i]; }

    // Hillis-Steele inclusive scan over 1024 thread sums
    sp[tid] = s;
    __syncthreads();
    int v = s;
    for (int o = 1; o < TPB_C; o <<= 1) {
        int add = (tid >= o) ? sp[tid - o] : 0;
        __syncthreads();
        v += add;
        sp[tid] = v;
        __syncthreads();
    }
    const int excl = v - s;

    if (excl < TOP_K && v >= TOP_K) {
        int cum = excl;
        #pragma unroll
        for (int i = 0; i < BPT; i++) {
            cum += bins[i];
            if (cum >= TOP_K) { s_bstar = b0 + i; break; }
        }
    }
    __syncthreads();
    const unsigned kmax = (unsigned)s_bstar;

    const int base = blockIdx.x * ROWS_C;
    const int rows = min(ROWS_C, N_DB - base);
    for (int j = tid; j < rows; j += TPB_C) {
        float d = g_dist[base + j];
        if ((__float_as_uint(d) >> HSHIFT) <= kmax) {
            int p = atomicAdd(&g_cnt, 1);
            if (p < CAP) { g_cd[p] = d; g_ci[p] = base + j; }
        }
    }
    __syncthreads();

    // last-block election: make this block's candidate writes visible, then
    // count in. The block observing done == NBLK_C-1 sees all writes.
    if (tid == 0) {
        __threadfence();
        s_last = (atomicAdd(&g_done, 1) == NBLK_C - 1);
    }
    __syncthreads();
    if (!s_last) return;

    // ---- inline rank selection over ~50 candidates ----
    const int n = min(g_cnt, CAP);
    for (int j = tid; j < n; j += TPB_C) {
        cd[j] = g_cd[j];
        ci[j] = g_ci[j];
    }
    if (tid == 0) g_done = 0;                    // reset for next replay
    __syncthreads();

    for (int t = tid; t < n; t += TPB_C) {
        float dt = cd[t];
        int   it = ci[t];
        int rank = 0;
        for (int j = 0; j < n; j++) {
            float dj = cd[j];
            int   ij = ci[j];
            rank += (dj < dt || (dj == dt && ij < it)) ? 1 : 0;
        }
        if (rank < TOP_K) { g_sel_d[rank] = dt; g_sel_i[rank] = it; }
    }
    __threadfence();
}

// ---------------------------------------------------------------------------
// Stage F: 33 blocks. Blocks 0-31 each gather one neighbor row (128 float4,
// latency parallel across SMs). Block 32 writes cls/dist and does scratch
// cleanup (histogram + counter). Output (all float32):
//   [0, 16384)     nbr_emb (32 x 512)
//   [16384, 16416) nbr_cls (int32 cast to float)
//   [16416, 16448) nbr_dist (ascending)
// ---------------------------------------------------------------------------
__global__ void __launch_bounds__(TPB_F)
knn_finish(const float* __restrict__ emb, const int* __restrict__ cls,
           float* __restrict__ out)
{
    const int tid = threadIdx.x;
    const int b   = blockIdx.x;

    if (b < TOP_K) {
        const int row = g_sel_i[b];
        const float4* src = (const float4*)(emb + (size_t)row * D_EMB);
        float4*       dst = (float4*)(out + (size_t)b * D_EMB);
        dst[tid] = src[tid];                      // 128 threads x 1 float4
    } else {
        if (tid < TOP_K) {
            int row = g_sel_i[tid];
            out[TOP_K * D_EMB + tid]         = (float)cls[row];
            out[TOP_K * D_EMB + TOP_K + tid] = sqrtf(g_sel_d[tid]);
        }
        if (tid == 0) g_cnt = 0;
        int4* h4 = (int4*)g_hist;
        const int4 z = make_int4(0, 0, 0, 0);
        for (int i = tid; i < NBINS / 4; i += TPB_F) h4[i] = z;
    }
}

extern "C" void kernel_launch(void* const* d_in, const int* in_sizes, int n_in,
                              void* d_out, int out_size)
{
    const float* x   = (const float*)d_in[0];      // [1, 512] f32
    const float* emb = (const float*)d_in[1];      // [200000, 512] f32
    const int*   cls = (const int*)d_in[2];        // [200000] int32
    // d_in[3] is k (scalar), fixed at 32
    float* out = (float*)d_out;

    knn_dist<<<NBLK_A, TPB_A>>>(x, emb);
    knn_hist<<<NBLK_H, TPB_H>>>();
    knn_compact_select<<<NBLK_C, TPB_C>>>();
    knn_finish<<<TOP_K + 1, TPB_F>>>(emb, cls, out);
}